// round 1
// baseline (speedup 1.0000x reference)
#include <cuda_runtime.h>
#include <math.h>

// Problem constants
#define B_ 2048
#define T_ 128
#define C_ 256
#define H_ 64
#define CK 64     // C-chunk per staging pass
#define NT 512    // threads per block

// ---- packed f32x2 helpers (ptxas will not auto-fuse; PTX only) ----
__device__ __forceinline__ unsigned long long pk2(float x, float y) {
    unsigned long long r;
    asm("mov.b64 %0, {%1, %2};" : "=l"(r) : "f"(x), "f"(y));
    return r;
}
__device__ __forceinline__ unsigned long long ffma2(unsigned long long a,
                                                    unsigned long long b,
                                                    unsigned long long c) {
    unsigned long long d;
    asm("fma.rn.f32x2 %0, %1, %2, %3;" : "=l"(d) : "l"(a), "l"(b), "l"(c));
    return d;
}
__device__ __forceinline__ float2 upk2(unsigned long long a) {
    float2 f;
    asm("mov.b64 {%0, %1}, %2;" : "=f"(f.x), "=f"(f.y) : "l"(a));
    return f;
}

// Shared memory layout (floats):
//   Qs [128][66]  Ks [128][66]  Vs [128][66]           : 3 * 8448 = 25344
//   union {
//     { XsT [64][130] (8320) ; Ws [3][64][64] (12288) } : 20608   (phase 1)
//     WeiT [128 s][130 t]                               : 16640   (phase 2/3)
//   }
// total = 45952 floats = 183808 bytes
#define QKV_STRIDE 66
#define QS_OFF 0
#define KS_OFF (128 * QKV_STRIDE)
#define VS_OFF (2 * 128 * QKV_STRIDE)
#define UN_OFF (3 * 128 * QKV_STRIDE)
#define XST_STRIDE 130
#define XST_OFF UN_OFF
#define WS_OFF (UN_OFF + CK * XST_STRIDE)
#define WEI_STRIDE 130
#define WEI_OFF UN_OFF
#define SMEM_FLOATS (UN_OFF + CK * XST_STRIDE + 3 * CK * H_)
#define SMEM_BYTES (SMEM_FLOATS * 4)

__global__ void __launch_bounds__(NT, 1)
head_kernel(const float* __restrict__ x,
            const float* __restrict__ Wk,
            const float* __restrict__ Wq,
            const float* __restrict__ Wv,
            float* __restrict__ out)
{
    extern __shared__ float sm[];
    float* Qs   = sm + QS_OFF;
    float* Ks   = sm + KS_OFF;
    float* Vs   = sm + VS_OFF;
    float* XsT  = sm + XST_OFF;
    float* Ws   = sm + WS_OFF;
    float* WeiT = sm + WEI_OFF;

    const int b   = blockIdx.x;
    const int tid = threadIdx.x;
    const float* xb = x + (size_t)b * (T_ * C_);

    const int h  = tid & 63;       // head dim this thread owns
    const int tg = tid >> 6;       // t-group 0..7 (16 rows each)
    const int t0 = tg * 16;

    // ---------------- Phase 1: Q/K/V projections -------------------------
    // Register accumulators: 8 f32x2 pairs over t (16 rows) per matrix.
    unsigned long long aq[8], ak[8], av[8];
#pragma unroll
    for (int i = 0; i < 8; i++) { aq[i] = 0ull; ak[i] = 0ull; av[i] = 0ull; }

    for (int ci = 0; ci < C_; ci += CK) {
        // Stage x chunk transposed: XsT[c][t]
#pragma unroll
        for (int k = 0; k < (T_ * CK) / NT; k++) {
            int idx = tid + k * NT;
            int t = idx >> 6;
            int c = idx & 63;
            XsT[c * XST_STRIDE + t] = xb[t * C_ + ci + c];
        }
        // Stage W chunks: Ws[m][c][h], m: 0=K, 1=Q, 2=V (input order)
#pragma unroll
        for (int k = 0; k < (3 * CK * H_) / NT; k++) {
            int idx = tid + k * NT;
            int m = idx >> 12;          // 0..2
            int rem = idx & 4095;       // c*64 + h
            const float* Wm = (m == 0) ? Wk : ((m == 1) ? Wq : Wv);
            Ws[idx] = Wm[ci * H_ + rem];
        }
        __syncthreads();

#pragma unroll 4
        for (int c = 0; c < CK; c++) {
            float wk = Ws[0 * (CK * H_) + c * H_ + h];
            float wq = Ws[1 * (CK * H_) + c * H_ + h];
            float wv = Ws[2 * (CK * H_) + c * H_ + h];
            unsigned long long wk2 = pk2(wk, wk);
            unsigned long long wq2 = pk2(wq, wq);
            unsigned long long wv2 = pk2(wv, wv);
            const unsigned long long* xr =
                (const unsigned long long*)&XsT[c * XST_STRIDE + t0];
#pragma unroll
            for (int i = 0; i < 8; i++) {
                unsigned long long xv = xr[i];
                ak[i] = ffma2(wk2, xv, ak[i]);
                aq[i] = ffma2(wq2, xv, aq[i]);
                av[i] = ffma2(wv2, xv, av[i]);
            }
        }
        __syncthreads();
    }

    // Spill projections to SMEM for phase 2/3.
#pragma unroll
    for (int i = 0; i < 8; i++) {
        int t = t0 + 2 * i;
        float2 q = upk2(aq[i]);
        float2 k = upk2(ak[i]);
        float2 v = upk2(av[i]);
        Qs[t * QKV_STRIDE + h] = q.x;  Qs[(t + 1) * QKV_STRIDE + h] = q.y;
        Ks[t * QKV_STRIDE + h] = k.x;  Ks[(t + 1) * QKV_STRIDE + h] = k.y;
        Vs[t * QKV_STRIDE + h] = v.x;  Vs[(t + 1) * QKV_STRIDE + h] = v.y;
    }
    __syncthreads();

    // ---------------- Phase 2: S = scale * Q K^T, causal softmax ---------
    const int warp = tid >> 5;
    const int lane = tid & 31;
    const float scale = 0.0625f;  // C^-0.5 = 1/16

    for (int r = 0; r < 8; r++) {
        int t = r * 16 + warp;          // uniform across warp
        int jmax = t >> 5;              // causal pruning of s-groups

        unsigned long long acc2[4] = {0ull, 0ull, 0ull, 0ull};
#pragma unroll 8
        for (int hh = 0; hh < H_; hh += 2) {
            unsigned long long q2 =
                *(const unsigned long long*)&Qs[t * QKV_STRIDE + hh];
#pragma unroll
            for (int j = 0; j < 4; j++) {
                if (j <= jmax) {
                    int s = lane + 32 * j;
                    unsigned long long k2 =
                        *(const unsigned long long*)&Ks[s * QKV_STRIDE + hh];
                    acc2[j] = ffma2(q2, k2, acc2[j]);
                }
            }
        }

        float val[4];
        float mx = -1e30f;
#pragma unroll
        for (int j = 0; j < 4; j++) {
            float2 a = upk2(acc2[j]);
            int s = lane + 32 * j;
            float v = (j <= jmax && s <= t) ? (a.x + a.y) * scale : -1e30f;
            val[j] = v;
            mx = fmaxf(mx, v);
        }
#pragma unroll
        for (int o = 16; o; o >>= 1)
            mx = fmaxf(mx, __shfl_xor_sync(0xFFFFFFFFu, mx, o));

        float p[4];
        float sum = 0.f;
#pragma unroll
        for (int j = 0; j < 4; j++) {
            p[j] = (val[j] > -1e29f) ? __expf(val[j] - mx) : 0.f;
            sum += p[j];
        }
#pragma unroll
        for (int o = 16; o; o >>= 1)
            sum += __shfl_xor_sync(0xFFFFFFFFu, sum, o);
        float inv = 1.f / sum;

#pragma unroll
        for (int j = 0; j < 4; j++) {
            int s = lane + 32 * j;
            WeiT[s * WEI_STRIDE + t] = p[j] * inv;   // transposed: [s][t]
        }
    }
    __syncthreads();

    // ---------------- Phase 3: out = Wei @ V ------------------------------
    unsigned long long acc[8];
#pragma unroll
    for (int i = 0; i < 8; i++) acc[i] = 0ull;

    const int smax = t0 + 15;   // wei[t][s] = 0 for s > t; t <= t0+15 here
    for (int s = 0; s <= smax; s++) {
        float v = Vs[s * QKV_STRIDE + h];
        unsigned long long v2 = pk2(v, v);
        const unsigned long long* wr =
            (const unsigned long long*)&WeiT[s * WEI_STRIDE + t0];
#pragma unroll
        for (int i = 0; i < 8; i++)
            acc[i] = ffma2(wr[i], v2, acc[i]);
    }

    float* ob = out + (size_t)b * (T_ * H_);
#pragma unroll
    for (int i = 0; i < 8; i++) {
        float2 a = upk2(acc[i]);
        ob[(t0 + 2 * i) * H_ + h]     = a.x;
        ob[(t0 + 2 * i + 1) * H_ + h] = a.y;
    }
}

extern "C" void kernel_launch(void* const* d_in, const int* in_sizes, int n_in,
                              void* d_out, int out_size) {
    const float* x  = (const float*)d_in[0];
    const float* Wk = (const float*)d_in[1];
    const float* Wq = (const float*)d_in[2];
    const float* Wv = (const float*)d_in[3];
    float* out = (float*)d_out;

    cudaFuncSetAttribute(head_kernel,
                         cudaFuncAttributeMaxDynamicSharedMemorySize,
                         SMEM_BYTES);
    head_kernel<<<B_, NT, SMEM_BYTES>>>(x, Wk, Wq, Wv, out);
}

// round 3
// speedup vs baseline: 2.0587x; 2.0587x over previous
#include <cuda_runtime.h>
#include <cuda_bf16.h>
#include <cstdint>

#define B_ 2048
#define T_ 128
#define C_ 256
#define H_ 64
#define NT 256

// ---- SMEM layout (bytes). Projection region is overlaid by attention tiles.
#define SM_XH 0          // X hi  [128][256] bf16, 512B/row  (64KB)
#define SM_XL 65536      // X lo                              (64KB)
#define SM_W  131072     // W  hi [64][256] 512B/row (32KB), lo at +32768
// after projection (overlay):
#define SM_QH 0          // [128][64] bf16, 128B/row (16KB), lo at +16384
#define SM_KH 32768
#define SM_VH 65536
#define SM_PH 98304      // [128][128] bf16, 256B/row (32KB), lo at +32768
#define SMEM_BYTES 196608

// W^T bf16 hi/lo, [3][64][256], produced once by prep kernel
__device__ __nv_bfloat16 g_Wth[3 * 64 * 256];
__device__ __nv_bfloat16 g_Wtl[3 * 64 * 256];

// ---- PTX helpers ----------------------------------------------------------
__device__ __forceinline__ uint32_t smem_u32(const void* p) {
    uint32_t a;
    asm("{ .reg .u64 t; cvta.to.shared.u64 t, %1; cvt.u32.u64 %0, t; }"
        : "=r"(a) : "l"(p));
    return a;
}
__device__ __forceinline__ void ldm4(uint32_t* r, uint32_t addr) {
    asm volatile("ldmatrix.sync.aligned.m8n8.x4.shared.b16 {%0,%1,%2,%3}, [%4];"
                 : "=r"(r[0]), "=r"(r[1]), "=r"(r[2]), "=r"(r[3]) : "r"(addr));
}
__device__ __forceinline__ void ldm4t(uint32_t* r, uint32_t addr) {
    asm volatile("ldmatrix.sync.aligned.m8n8.x4.trans.shared.b16 {%0,%1,%2,%3}, [%4];"
                 : "=r"(r[0]), "=r"(r[1]), "=r"(r[2]), "=r"(r[3]) : "r"(addr));
}
__device__ __forceinline__ void mma16816(float* d, const uint32_t* a,
                                         uint32_t b0, uint32_t b1) {
    asm("mma.sync.aligned.m16n8k16.row.col.f32.bf16.bf16.f32 "
        "{%0,%1,%2,%3}, {%4,%5,%6,%7}, {%8,%9}, {%0,%1,%2,%3};"
        : "+f"(d[0]), "+f"(d[1]), "+f"(d[2]), "+f"(d[3])
        : "r"(a[0]), "r"(a[1]), "r"(a[2]), "r"(a[3]), "r"(b0), "r"(b1));
}
// pack (lo -> lower half, hi -> upper half)
__device__ __forceinline__ uint32_t pack_bf2(float lo, float hi) {
    uint32_t r;
    asm("cvt.rn.bf16x2.f32 %0, %1, %2;" : "=r"(r) : "f"(hi), "f"(lo));
    return r;
}
__device__ __forceinline__ void split_pack(float a, float b,
                                           uint32_t& hp, uint32_t& lp) {
    __nv_bfloat16 ha = __float2bfloat16_rn(a), hb = __float2bfloat16_rn(b);
    hp = pack_bf2(a, b);
    lp = pack_bf2(a - __bfloat162float(ha), b - __bfloat162float(hb));
}
// swizzled 16B-chunk offset within a row
#define SWC(chunk, row) ((((chunk) ^ ((row) & 7)) << 4))

// ---- prep kernel: W[c][h] fp32 -> W^T[h][c] bf16 hi/lo --------------------
__global__ void prep_w(const float* __restrict__ Wk,
                       const float* __restrict__ Wq,
                       const float* __restrict__ Wv)
{
    int idx = blockIdx.x * 256 + threadIdx.x;   // 49152 total
    int m = idx >> 14;
    int r = idx & 16383;
    int h = r >> 8, c = r & 255;
    const float* W = (m == 0) ? Wk : ((m == 1) ? Wq : Wv);
    float v = W[c * 64 + h];
    __nv_bfloat16 hb = __float2bfloat16_rn(v);
    g_Wth[idx] = hb;
    g_Wtl[idx] = __float2bfloat16_rn(v - __bfloat162float(hb));
}

// ---- main kernel ----------------------------------------------------------
__global__ void __launch_bounds__(NT, 1)
head_mma(const float* __restrict__ x, float* __restrict__ out)
{
    extern __shared__ char sm[];
    const uint32_t smb = smem_u32(sm);
    const int tid = threadIdx.x, lane = tid & 31, wid = tid >> 5;
    const float* xb = x + (size_t)blockIdx.x * (T_ * C_);

    // ---- stage X -> bf16 hi/lo (swizzled) ----
#pragma unroll 8
    for (int it = 0; it < 64; it++) {
        int u = tid + (it << 8);          // float2 index; 16384 total
        int row = u >> 7, cp = u & 127;
        float2 v = *(const float2*)(xb + 2 * u);
        uint32_t h, l;
        split_pack(v.x, v.y, h, l);
        uint32_t off = row * 512 + SWC(cp >> 2, row) + ((cp & 3) << 2);
        *(uint32_t*)(sm + SM_XH + off) = h;
        *(uint32_t*)(sm + SM_XL + off) = l;
    }

    // ---- projections: per-matrix [128x64] = X[128x256] @ W[256x64] ----
    float pacc[3][2][4][4];
#pragma unroll
    for (int m = 0; m < 3; m++)
#pragma unroll
        for (int mt = 0; mt < 2; mt++)
#pragma unroll
            for (int nt = 0; nt < 4; nt++)
#pragma unroll
                for (int i = 0; i < 4; i++) pacc[m][mt][nt][i] = 0.f;

    const int mr = (wid & 3) * 32;      // warp M-block
    const int nc = (wid >> 2) * 32;     // warp N-block

#pragma unroll
    for (int m = 0; m < 3; m++) {
        __syncthreads();                // W region free (and X staged, for m=0)
        const uint32_t* srcH = (const uint32_t*)(g_Wth + m * 16384);
        const uint32_t* srcL = (const uint32_t*)(g_Wtl + m * 16384);
#pragma unroll 8
        for (int it = 0; it < 32; it++) {
            int u = tid + (it << 8);     // u32-pair index; 8192 total
            int hr = u >> 7, cp = u & 127;
            uint32_t off = hr * 512 + SWC(cp >> 2, hr) + ((cp & 3) << 2);
            *(uint32_t*)(sm + SM_W + off) = srcH[u];
            *(uint32_t*)(sm + SM_W + 32768 + off) = srcL[u];
        }
        __syncthreads();

#pragma unroll 4
        for (int ks = 0; ks < 16; ks++) {
            uint32_t ah[2][4], al[2][4], bh[2][4], bl[2][4];
#pragma unroll
            for (int mt = 0; mt < 2; mt++) {
                int ar = mr + 16 * mt + (lane & 15);
                uint32_t ad = smb + SM_XH + ar * 512
                            + SWC(2 * ks + (lane >> 4), ar);
                ldm4(ah[mt], ad);
                ldm4(al[mt], ad + 65536);
            }
#pragma unroll
            for (int n16 = 0; n16 < 2; n16++) {
                int bn = nc + 16 * n16 + ((lane >> 3) & 1) * 8 + (lane & 7);
                uint32_t bd = smb + SM_W + bn * 512
                            + SWC(2 * ks + (lane >> 4), bn);
                ldm4(bh[n16], bd);
                ldm4(bl[n16], bd + 32768);
            }
#pragma unroll
            for (int mt = 0; mt < 2; mt++)
#pragma unroll
                for (int n16 = 0; n16 < 2; n16++)
#pragma unroll
                    for (int j = 0; j < 2; j++) {
                        float* d = pacc[m][mt][2 * n16 + j];
                        mma16816(d, ah[mt], bh[n16][j], bh[n16][j + 2]);
                        mma16816(d, ah[mt], bl[n16][j], bl[n16][j + 2]);
                        mma16816(d, al[mt], bh[n16][j], bh[n16][j + 2]);
                    }
        }
    }
    __syncthreads();    // all proj MMAs done; X/W regions now reusable

    // ---- spill Q/K/V as bf16 hi/lo tiles [row][h], 128B rows -------------
#pragma unroll
    for (int m = 0; m < 3; m++) {
        uint32_t base = (m == 0) ? SM_KH : ((m == 1) ? SM_QH : SM_VH);
#pragma unroll
        for (int mt = 0; mt < 2; mt++)
#pragma unroll
            for (int nt = 0; nt < 4; nt++) {
                float* d = pacc[m][mt][nt];
                int ra = mr + 16 * mt + (lane >> 2), rb = ra + 8;
                int c = nc + 8 * nt + 2 * (lane & 3);
                uint32_t h0, l0, h1, l1;
                split_pack(d[0], d[1], h0, l0);
                split_pack(d[2], d[3], h1, l1);
                uint32_t o0 = ra * 128 + SWC(c >> 3, ra) + ((c & 7) << 1);
                uint32_t o1 = rb * 128 + SWC(c >> 3, rb) + ((c & 7) << 1);
                *(uint32_t*)(sm + base + o0) = h0;
                *(uint32_t*)(sm + base + 16384 + o0) = l0;
                *(uint32_t*)(sm + base + o1) = h1;
                *(uint32_t*)(sm + base + 16384 + o1) = l1;
            }
    }
    __syncthreads();

    // ---- S = Q K^T with causal n-tile skipping ---------------------------
    float sacc[16][4];
#pragma unroll
    for (int nt = 0; nt < 16; nt++)
#pragma unroll
        for (int i = 0; i < 4; i++) sacc[nt][i] = 0.f;

    const int r16 = wid * 16;
#pragma unroll
    for (int ks = 0; ks < 4; ks++) {
        int ar = r16 + (lane & 15);
        uint32_t ad = smb + SM_QH + ar * 128 + SWC(2 * ks + (lane >> 4), ar);
        uint32_t qh[4], ql[4];
        ldm4(qh, ad);
        ldm4(ql, ad + 16384);
#pragma unroll
        for (int n16 = 0; n16 < 8; n16++) {
            if (n16 <= wid) {
                int bn = 16 * n16 + ((lane >> 3) & 1) * 8 + (lane & 7);
                uint32_t bd = smb + SM_KH + bn * 128
                            + SWC(2 * ks + (lane >> 4), bn);
                uint32_t kh[4], kl[4];
                ldm4(kh, bd);
                ldm4(kl, bd + 16384);
#pragma unroll
                for (int j = 0; j < 2; j++) {
                    float* dd = sacc[2 * n16 + j];
                    mma16816(dd, qh, kh[j], kh[j + 2]);
                    mma16816(dd, qh, kl[j], kl[j + 2]);
                    mma16816(dd, ql, kh[j], kh[j + 2]);
                }
            }
        }
    }

    // ---- causal softmax in registers ------------------------------------
    const int ra = r16 + (lane >> 2), rb = ra + 8;
    float mxa = -1e30f, mxb = -1e30f;
#pragma unroll
    for (int nt = 0; nt < 16; nt++) {
        bool act = (nt >> 1) <= wid;
        int c0 = 8 * nt + 2 * (lane & 3);
        float s0 = (act && c0 <= ra)     ? sacc[nt][0] * 0.0625f : -1e30f;
        float s1 = (act && c0 + 1 <= ra) ? sacc[nt][1] * 0.0625f : -1e30f;
        float s2 = (act && c0 <= rb)     ? sacc[nt][2] * 0.0625f : -1e30f;
        float s3 = (act && c0 + 1 <= rb) ? sacc[nt][3] * 0.0625f : -1e30f;
        sacc[nt][0] = s0; sacc[nt][1] = s1; sacc[nt][2] = s2; sacc[nt][3] = s3;
        mxa = fmaxf(mxa, fmaxf(s0, s1));
        mxb = fmaxf(mxb, fmaxf(s2, s3));
    }
    mxa = fmaxf(mxa, __shfl_xor_sync(0xFFFFFFFFu, mxa, 1));
    mxa = fmaxf(mxa, __shfl_xor_sync(0xFFFFFFFFu, mxa, 2));
    mxb = fmaxf(mxb, __shfl_xor_sync(0xFFFFFFFFu, mxb, 1));
    mxb = fmaxf(mxb, __shfl_xor_sync(0xFFFFFFFFu, mxb, 2));

    float suma = 0.f, sumb = 0.f;
#pragma unroll
    for (int nt = 0; nt < 16; nt++) {
        float e0 = (sacc[nt][0] > -1e29f) ? __expf(sacc[nt][0] - mxa) : 0.f;
        float e1 = (sacc[nt][1] > -1e29f) ? __expf(sacc[nt][1] - mxa) : 0.f;
        float e2 = (sacc[nt][2] > -1e29f) ? __expf(sacc[nt][2] - mxb) : 0.f;
        float e3 = (sacc[nt][3] > -1e29f) ? __expf(sacc[nt][3] - mxb) : 0.f;
        sacc[nt][0] = e0; sacc[nt][1] = e1; sacc[nt][2] = e2; sacc[nt][3] = e3;
        suma += e0 + e1;
        sumb += e2 + e3;
    }
    suma += __shfl_xor_sync(0xFFFFFFFFu, suma, 1);
    suma += __shfl_xor_sync(0xFFFFFFFFu, suma, 2);
    sumb += __shfl_xor_sync(0xFFFFFFFFu, sumb, 1);
    sumb += __shfl_xor_sync(0xFFFFFFFFu, sumb, 2);
    float inva = 1.f / suma, invb = 1.f / sumb;

    // ---- P -> bf16 hi/lo tile [t][s], 256B rows --------------------------
#pragma unroll
    for (int nt = 0; nt < 16; nt++) {
        if ((nt >> 1) <= wid) {
            int c0 = 8 * nt + 2 * (lane & 3);
            uint32_t h0, l0, h1, l1;
            split_pack(sacc[nt][0] * inva, sacc[nt][1] * inva, h0, l0);
            split_pack(sacc[nt][2] * invb, sacc[nt][3] * invb, h1, l1);
            uint32_t o0 = ra * 256 + SWC(c0 >> 3, ra) + ((c0 & 7) << 1);
            uint32_t o1 = rb * 256 + SWC(c0 >> 3, rb) + ((c0 & 7) << 1);
            *(uint32_t*)(sm + SM_PH + o0) = h0;
            *(uint32_t*)(sm + SM_PH + 32768 + o0) = l0;
            *(uint32_t*)(sm + SM_PH + o1) = h1;
            *(uint32_t*)(sm + SM_PH + 32768 + o1) = l1;
        }
    }
    __syncwarp();   // P rows are private to this warp

    // ---- O = P V with causal k-step skipping -----------------------------
    float oacc[8][4];
#pragma unroll
    for (int nt = 0; nt < 8; nt++)
#pragma unroll
        for (int i = 0; i < 4; i++) oacc[nt][i] = 0.f;

#pragma unroll
    for (int ks = 0; ks < 8; ks++) {
        if (ks <= wid) {
            int par = r16 + (lane & 15);
            uint32_t ad = smb + SM_PH + par * 256
                        + SWC(2 * ks + (lane >> 4), par);
            uint32_t ph[4], pl[4];
            ldm4(ph, ad);
            ldm4(pl, ad + 32768);
#pragma unroll
            for (int ntv = 0; ntv < 4; ntv++) {
                int vr = 16 * ks + (lane & 15);
                uint32_t vd = smb + SM_VH + vr * 128
                            + SWC(2 * ntv + (lane >> 4), vr);
                uint32_t vh[4], vl[4];
                ldm4t(vh, vd);
                ldm4t(vl, vd + 16384);
#pragma unroll
                for (int j = 0; j < 2; j++) {
                    float* dd = oacc[2 * ntv + j];
                    mma16816(dd, ph, vh[2 * j], vh[2 * j + 1]);
                    mma16816(dd, ph, vl[2 * j], vl[2 * j + 1]);
                    mma16816(dd, pl, vh[2 * j], vh[2 * j + 1]);
                }
            }
        }
    }

    // ---- write out -------------------------------------------------------
    float* ob = out + (size_t)blockIdx.x * (T_ * H_);
#pragma unroll
    for (int nt = 0; nt < 8; nt++) {
        int c0 = 8 * nt + 2 * (lane & 3);
        float2 v0 = make_float2(oacc[nt][0], oacc[nt][1]);
        float2 v1 = make_float2(oacc[nt][2], oacc[nt][3]);
        *(float2*)(ob + ra * 64 + c0) = v0;
        *(float2*)(ob + rb * 64 + c0) = v1;
    }
}

extern "C" void kernel_launch(void* const* d_in, const int* in_sizes, int n_in,
                              void* d_out, int out_size) {
    const float* x  = (const float*)d_in[0];
    const float* Wk = (const float*)d_in[1];
    const float* Wq = (const float*)d_in[2];
    const float* Wv = (const float*)d_in[3];
    float* out = (float*)d_out;

    prep_w<<<192, 256>>>(Wk, Wq, Wv);

    cudaFuncSetAttribute(head_mma,
                         cudaFuncAttributeMaxDynamicSharedMemorySize,
                         SMEM_BYTES);
    head_mma<<<B_, NT, SMEM_BYTES>>>(x, out);
}

// round 4
// speedup vs baseline: 2.2472x; 1.0916x over previous
#include <cuda_runtime.h>
#include <cuda_bf16.h>
#include <cstdint>

#define B_ 2048
#define T_ 128
#define C_ 256
#define H_ 64
#define NT 256

// ---- SMEM (bytes), total 96KB. Proj region overlaid by attention region. --
// proj:  XH [128][128]bf16 (256B rows) 32KB @0, XL @32768,
//        WH [64][128] (256B rows) 16KB @65536, WL @81920
// attn:  KH @0 16KB, KL @16384, VH @32768, VL @49152,
//        QH @65536 (later P hi), QL @81920 (later P lo)   [128][64], 128B rows
#define SM_XH 0
#define SM_XL 32768
#define SM_WH 65536
#define SM_WL 81920
#define SM_KH 0
#define SM_KL 16384
#define SM_VH 32768
#define SM_VL 49152
#define SM_QH 65536   // reused as P hi after Q fragments are loaded
#define SM_QL 81920   // reused as P lo
#define SMEM_BYTES 98304

// W^T bf16 hi/lo, [3][64][256], produced once by prep kernel
__device__ __nv_bfloat16 g_Wth[3 * 64 * 256];
__device__ __nv_bfloat16 g_Wtl[3 * 64 * 256];

// ---- PTX helpers ----------------------------------------------------------
__device__ __forceinline__ uint32_t smem_u32(const void* p) {
    uint32_t a;
    asm("{ .reg .u64 t; cvta.to.shared.u64 t, %1; cvt.u32.u64 %0, t; }"
        : "=r"(a) : "l"(p));
    return a;
}
__device__ __forceinline__ void ldm4(uint32_t* r, uint32_t addr) {
    asm volatile("ldmatrix.sync.aligned.m8n8.x4.shared.b16 {%0,%1,%2,%3}, [%4];"
                 : "=r"(r[0]), "=r"(r[1]), "=r"(r[2]), "=r"(r[3]) : "r"(addr));
}
__device__ __forceinline__ void ldm4t(uint32_t* r, uint32_t addr) {
    asm volatile("ldmatrix.sync.aligned.m8n8.x4.trans.shared.b16 {%0,%1,%2,%3}, [%4];"
                 : "=r"(r[0]), "=r"(r[1]), "=r"(r[2]), "=r"(r[3]) : "r"(addr));
}
__device__ __forceinline__ void mma16816(float* d, const uint32_t* a,
                                         uint32_t b0, uint32_t b1) {
    asm("mma.sync.aligned.m16n8k16.row.col.f32.bf16.bf16.f32 "
        "{%0,%1,%2,%3}, {%4,%5,%6,%7}, {%8,%9}, {%0,%1,%2,%3};"
        : "+f"(d[0]), "+f"(d[1]), "+f"(d[2]), "+f"(d[3])
        : "r"(a[0]), "r"(a[1]), "r"(a[2]), "r"(a[3]), "r"(b0), "r"(b1));
}
__device__ __forceinline__ uint32_t pack_bf2(float lo, float hi) {
    uint32_t r;
    asm("cvt.rn.bf16x2.f32 %0, %1, %2;" : "=r"(r) : "f"(hi), "f"(lo));
    return r;
}
__device__ __forceinline__ void split_pack(float a, float b,
                                           uint32_t& hp, uint32_t& lp) {
    __nv_bfloat16 ha = __float2bfloat16_rn(a), hb = __float2bfloat16_rn(b);
    hp = pack_bf2(a, b);
    lp = pack_bf2(a - __bfloat162float(ha), b - __bfloat162float(hb));
}
// swizzled 16B-chunk offset within a row (chunk 0..15, conflict-free ldmatrix)
#define SWC(chunk, row) ((((chunk) ^ ((row) & 7)) << 4))

// ---- prep kernel: W[c][h] fp32 -> W^T[h][c] bf16 hi/lo --------------------
__global__ void prep_w(const float* __restrict__ Wk,
                       const float* __restrict__ Wq,
                       const float* __restrict__ Wv)
{
    int idx = blockIdx.x * 256 + threadIdx.x;   // 49152 total
    int m = idx >> 14;
    int r = idx & 16383;
    int h = r >> 8, c = r & 255;
    const float* W = (m == 0) ? Wk : ((m == 1) ? Wq : Wv);
    float v = W[c * 64 + h];
    __nv_bfloat16 hb = __float2bfloat16_rn(v);
    g_Wth[idx] = hb;
    g_Wtl[idx] = __float2bfloat16_rn(v - __bfloat162float(hb));
}

// ---- main kernel ----------------------------------------------------------
__global__ void __launch_bounds__(NT, 2)
head_mma(const float* __restrict__ x, float* __restrict__ out)
{
    extern __shared__ char sm[];
    const uint32_t smb = smem_u32(sm);
    const int tid = threadIdx.x, lane = tid & 31, wid = tid >> 5;
    const float* xb = x + (size_t)blockIdx.x * (T_ * C_);

    // ================= Phase 1: QKV projections (K in 2 chunks) ===========
    float pacc[3][2][4][4];
#pragma unroll
    for (int m = 0; m < 3; m++)
#pragma unroll
        for (int mt = 0; mt < 2; mt++)
#pragma unroll
            for (int nt = 0; nt < 4; nt++)
#pragma unroll
                for (int i = 0; i < 4; i++) pacc[m][mt][nt][i] = 0.f;

    const int mr = (wid & 3) * 32;      // warp M-block (rows)
    const int nc = (wid >> 2) * 32;     // warp N-block (cols within matrix)

#pragma unroll
    for (int chunk = 0; chunk < 2; chunk++) {
        __syncthreads();   // previous chunk's MMAs done -> X/W writable

        // stage X chunk [128 rows][128 cols] fp32 -> bf16 h/l swizzled
#pragma unroll 4
        for (int it = 0; it < 32; it++) {
            int u = tid + (it << 8);          // float2 index, 8192 total
            int row = u >> 6, cp = u & 63;
            float2 v = *(const float2*)(xb + row * C_ + chunk * 128 + 2 * cp);
            uint32_t h, l;
            split_pack(v.x, v.y, h, l);
            uint32_t off = row * 256 + SWC(cp >> 2, row) + ((cp & 3) << 2);
            *(uint32_t*)(sm + SM_XH + off) = h;
            *(uint32_t*)(sm + SM_XL + off) = l;
        }

#pragma unroll
        for (int m = 0; m < 3; m++) {
            if (m > 0) __syncthreads();   // prev m's MMAs done -> W writable
            // stage W(m, chunk): [64 h-rows][128 cols] bf16 h/l
            const uint32_t* srcH = (const uint32_t*)(g_Wth + m * 16384);
            const uint32_t* srcL = (const uint32_t*)(g_Wtl + m * 16384);
#pragma unroll 4
            for (int it = 0; it < 16; it++) {
                int u = tid + (it << 8);      // u32-pair index, 4096 total
                int hr = u >> 6, cp = u & 63;
                uint32_t off = hr * 256 + SWC(cp >> 2, hr) + ((cp & 3) << 2);
                *(uint32_t*)(sm + SM_WH + off) = srcH[hr * 128 + chunk * 64 + cp];
                *(uint32_t*)(sm + SM_WL + off) = srcL[hr * 128 + chunk * 64 + cp];
            }
            __syncthreads();

#pragma unroll 2
            for (int ks = 0; ks < 8; ks++) {
                uint32_t ah[2][4], al[2][4];
#pragma unroll
                for (int mt = 0; mt < 2; mt++) {
                    int ar = mr + 16 * mt + (lane & 15);
                    uint32_t ad = smb + SM_XH + ar * 256
                                + SWC(2 * ks + (lane >> 4), ar);
                    ldm4(ah[mt], ad);
                    ldm4(al[mt], ad + 32768);
                }
#pragma unroll
                for (int n16 = 0; n16 < 2; n16++) {
                    uint32_t bh[4], bl[4];
                    int bn = nc + 16 * n16 + ((lane >> 3) & 1) * 8 + (lane & 7);
                    uint32_t bd = smb + SM_WH + bn * 256
                                + SWC(2 * ks + (lane >> 4), bn);
                    ldm4(bh, bd);
                    ldm4(bl, bd + 16384);
#pragma unroll
                    for (int mt = 0; mt < 2; mt++)
#pragma unroll
                        for (int j = 0; j < 2; j++) {
                            float* d = pacc[m][mt][2 * n16 + j];
                            mma16816(d, ah[mt], bh[j], bh[j + 2]);
                            mma16816(d, ah[mt], bl[j], bl[j + 2]);
                            mma16816(d, al[mt], bh[j], bh[j + 2]);
                        }
                }
            }
        }
    }
    __syncthreads();   // all proj MMAs done; overlay attn region

    // ---- spill K/Q/V as bf16 h/l tiles [row][h], Q pre-scaled by 2^-4 ----
#pragma unroll
    for (int m = 0; m < 3; m++) {
        uint32_t base = (m == 0) ? SM_KH : ((m == 1) ? SM_QH : SM_VH);
        float scale = (m == 1) ? 0.0625f : 1.0f;
#pragma unroll
        for (int mt = 0; mt < 2; mt++)
#pragma unroll
            for (int nt = 0; nt < 4; nt++) {
                float* d = pacc[m][mt][nt];
                int sra = mr + 16 * mt + (lane >> 2), srb = sra + 8;
                int c = nc + 8 * nt + 2 * (lane & 3);
                uint32_t h0, l0, h1, l1;
                split_pack(d[0] * scale, d[1] * scale, h0, l0);
                split_pack(d[2] * scale, d[3] * scale, h1, l1);
                uint32_t o0 = sra * 128 + SWC(c >> 3, sra) + ((c & 7) << 1);
                uint32_t o1 = srb * 128 + SWC(c >> 3, srb) + ((c & 7) << 1);
                *(uint32_t*)(sm + base + o0) = h0;
                *(uint32_t*)(sm + base + 16384 + o0) = l0;
                *(uint32_t*)(sm + base + o1) = h1;
                *(uint32_t*)(sm + base + 16384 + o1) = l1;
            }
    }
    __syncthreads();

    // ---- load Q fragments into registers (frees Q smem region for P) -----
    const int r16 = wid * 16;
    uint32_t qh[4][4], ql[4][4];
#pragma unroll
    for (int ks = 0; ks < 4; ks++) {
        int ar = r16 + (lane & 15);
        uint32_t ad = smb + SM_QH + ar * 128 + SWC(2 * ks + (lane >> 4), ar);
        ldm4(qh[ks], ad);
        ldm4(ql[ks], ad + 16384);
    }
    __syncthreads();   // everyone has Q; P may now overwrite

    // ================= Phase 2: flash-style attention ======================
    const int ra = r16 + (lane >> 2), rb = ra + 8;
    float m0 = -1e30f, m1 = -1e30f, l0 = 0.f, l1 = 0.f;
    float oacc[8][4];
#pragma unroll
    for (int nt = 0; nt < 8; nt++)
#pragma unroll
        for (int i = 0; i < 4; i++) oacc[nt][i] = 0.f;

    const int cmax = (wid < 4) ? 1 : 2;
    for (int c = 0; c < cmax; c++) {
        // ---- S chunk: rows [r16,r16+16) x cols [64c, 64c+64) ----
        float sacc[8][4];
#pragma unroll
        for (int nt = 0; nt < 8; nt++)
#pragma unroll
            for (int i = 0; i < 4; i++) sacc[nt][i] = 0.f;

#pragma unroll
        for (int ks = 0; ks < 4; ks++) {
#pragma unroll
            for (int n16 = 0; n16 < 4; n16++) {
                if (4 * c + n16 <= wid) {
                    int bn = 64 * c + 16 * n16
                           + ((lane >> 3) & 1) * 8 + (lane & 7);
                    uint32_t bd = smb + SM_KH + bn * 128
                                + SWC(2 * ks + (lane >> 4), bn);
                    uint32_t kh[4], kl[4];
                    ldm4(kh, bd);
                    ldm4(kl, bd + 16384);
#pragma unroll
                    for (int j = 0; j < 2; j++) {
                        float* dd = sacc[2 * n16 + j];
                        mma16816(dd, qh[ks], kh[j], kh[j + 2]);
                        mma16816(dd, qh[ks], kl[j], kl[j + 2]);
                        mma16816(dd, ql[ks], kh[j], kh[j + 2]);
                    }
                }
            }
        }

        // ---- causal mask + online softmax update (warp-local) ----
        float cm0 = -1e30f, cm1 = -1e30f;
#pragma unroll
        for (int nt = 0; nt < 8; nt++) {
            bool act = (4 * c + (nt >> 1)) <= wid;
            int s0 = 64 * c + 8 * nt + 2 * (lane & 3);
            float v0 = (act && s0 <= ra)     ? sacc[nt][0] : -1e30f;
            float v1 = (act && s0 + 1 <= ra) ? sacc[nt][1] : -1e30f;
            float v2 = (act && s0 <= rb)     ? sacc[nt][2] : -1e30f;
            float v3 = (act && s0 + 1 <= rb) ? sacc[nt][3] : -1e30f;
            sacc[nt][0] = v0; sacc[nt][1] = v1;
            sacc[nt][2] = v2; sacc[nt][3] = v3;
            cm0 = fmaxf(cm0, fmaxf(v0, v1));
            cm1 = fmaxf(cm1, fmaxf(v2, v3));
        }
        cm0 = fmaxf(cm0, __shfl_xor_sync(0xFFFFFFFFu, cm0, 1));
        cm0 = fmaxf(cm0, __shfl_xor_sync(0xFFFFFFFFu, cm0, 2));
        cm1 = fmaxf(cm1, __shfl_xor_sync(0xFFFFFFFFu, cm1, 1));
        cm1 = fmaxf(cm1, __shfl_xor_sync(0xFFFFFFFFu, cm1, 2));

        float mn0 = fmaxf(m0, cm0), mn1 = fmaxf(m1, cm1);
        float a0 = __expf(m0 - mn0), a1 = __expf(m1 - mn1);
        float cs0 = 0.f, cs1 = 0.f;
#pragma unroll
        for (int nt = 0; nt < 8; nt++) {
            float e0 = (sacc[nt][0] > -1e29f) ? __expf(sacc[nt][0] - mn0) : 0.f;
            float e1 = (sacc[nt][1] > -1e29f) ? __expf(sacc[nt][1] - mn0) : 0.f;
            float e2 = (sacc[nt][2] > -1e29f) ? __expf(sacc[nt][2] - mn1) : 0.f;
            float e3 = (sacc[nt][3] > -1e29f) ? __expf(sacc[nt][3] - mn1) : 0.f;
            sacc[nt][0] = e0; sacc[nt][1] = e1;
            sacc[nt][2] = e2; sacc[nt][3] = e3;
            cs0 += e0 + e1;
            cs1 += e2 + e3;
        }
        cs0 += __shfl_xor_sync(0xFFFFFFFFu, cs0, 1);
        cs0 += __shfl_xor_sync(0xFFFFFFFFu, cs0, 2);
        cs1 += __shfl_xor_sync(0xFFFFFFFFu, cs1, 1);
        cs1 += __shfl_xor_sync(0xFFFFFFFFu, cs1, 2);
        l0 = l0 * a0 + cs0;
        l1 = l1 * a1 + cs1;
        m0 = mn0; m1 = mn1;

        // rescale running O
#pragma unroll
        for (int nt = 0; nt < 8; nt++) {
            oacc[nt][0] *= a0; oacc[nt][1] *= a0;
            oacc[nt][2] *= a1; oacc[nt][3] *= a1;
        }

        // ---- store P chunk (warp-private rows) bf16 h/l ----
#pragma unroll
        for (int nt = 0; nt < 8; nt++) {
            if ((4 * c + (nt >> 1)) <= wid) {
                int c0 = 8 * nt + 2 * (lane & 3);   // chunk-local col
                uint32_t h0, lo0, h1, lo1;
                split_pack(sacc[nt][0], sacc[nt][1], h0, lo0);
                split_pack(sacc[nt][2], sacc[nt][3], h1, lo1);
                uint32_t o0 = ra * 128 + SWC(c0 >> 3, ra) + ((c0 & 7) << 1);
                uint32_t o1 = rb * 128 + SWC(c0 >> 3, rb) + ((c0 & 7) << 1);
                *(uint32_t*)(sm + SM_QH + o0) = h0;
                *(uint32_t*)(sm + SM_QL + o0) = lo0;
                *(uint32_t*)(sm + SM_QH + o1) = h1;
                *(uint32_t*)(sm + SM_QL + o1) = lo1;
            }
        }
        __syncwarp();

        // ---- O += P_chunk @ V_chunk ----
#pragma unroll
        for (int ks2 = 0; ks2 < 4; ks2++) {
            if (4 * c + ks2 <= wid) {
                int par = r16 + (lane & 15);
                uint32_t ad = smb + SM_QH + par * 128
                            + SWC(2 * ks2 + (lane >> 4), par);
                uint32_t ph[4], pl[4];
                ldm4(ph, ad);
                ldm4(pl, ad + 16384);
#pragma unroll
                for (int ntv = 0; ntv < 4; ntv++) {
                    int vr = 64 * c + 16 * ks2 + (lane & 15);
                    uint32_t vd = smb + SM_VH + vr * 128
                                + SWC(2 * ntv + (lane >> 4), vr);
                    uint32_t vh[4], vl[4];
                    ldm4t(vh, vd);
                    ldm4t(vl, vd + 16384);
#pragma unroll
                    for (int j = 0; j < 2; j++) {
                        float* dd = oacc[2 * ntv + j];
                        mma16816(dd, ph, vh[2 * j], vh[2 * j + 1]);
                        mma16816(dd, ph, vl[2 * j], vl[2 * j + 1]);
                        mma16816(dd, pl, vh[2 * j], vh[2 * j + 1]);
                    }
                }
            }
        }
        __syncwarp();   // P reads done before next chunk overwrites
    }

    // ---- normalize + write out -------------------------------------------
    float inv0 = 1.f / l0, inv1 = 1.f / l1;
    float* ob = out + (size_t)blockIdx.x * (T_ * H_);
#pragma unroll
    for (int nt = 0; nt < 8; nt++) {
        int c0 = 8 * nt + 2 * (lane & 3);
        *(float2*)(ob + ra * 64 + c0) =
            make_float2(oacc[nt][0] * inv0, oacc[nt][1] * inv0);
        *(float2*)(ob + rb * 64 + c0) =
            make_float2(oacc[nt][2] * inv1, oacc[nt][3] * inv1);
    }
}

extern "C" void kernel_launch(void* const* d_in, const int* in_sizes, int n_in,
                              void* d_out, int out_size) {
    const float* x  = (const float*)d_in[0];
    const float* Wk = (const float*)d_in[1];
    const float* Wq = (const float*)d_in[2];
    const float* Wv = (const float*)d_in[3];
    float* out = (float*)d_out;

    prep_w<<<192, 256>>>(Wk, Wq, Wv);

    cudaFuncSetAttribute(head_mma,
                         cudaFuncAttributeMaxDynamicSharedMemorySize,
                         SMEM_BYTES);
    head_mma<<<B_, NT, SMEM_BYTES>>>(x, out);
}

// round 5
// speedup vs baseline: 4.2685x; 1.8994x over previous
#include <cuda_runtime.h>
#include <cuda_fp16.h>
#include <cstdint>

#define B_ 2048
#define T_ 128
#define C_ 256
#define H_ 64
#define NT 256

// ---- SMEM (bytes), total 48KB. Proj region overlaid by attention region. --
// proj: X [128][128]fp16 (256B rows) 32KB @0, W [64][128] (256B rows) 16KB @32768
// attn: K @0 16KB, V @16384, Q @32768 (reused as P)   [128][64] fp16, 128B rows
#define SM_X 0
#define SM_W 32768
#define SM_K 0
#define SM_V 16384
#define SM_Q 32768
#define SMEM_BYTES 49152

// W^T fp16, [3][64][256], produced once by prep kernel
__device__ __half g_Wt[3 * 64 * 256];

// ---- PTX helpers ----------------------------------------------------------
__device__ __forceinline__ uint32_t smem_u32(const void* p) {
    uint32_t a;
    asm("{ .reg .u64 t; cvta.to.shared.u64 t, %1; cvt.u32.u64 %0, t; }"
        : "=r"(a) : "l"(p));
    return a;
}
__device__ __forceinline__ void ldm4(uint32_t* r, uint32_t addr) {
    asm volatile("ldmatrix.sync.aligned.m8n8.x4.shared.b16 {%0,%1,%2,%3}, [%4];"
                 : "=r"(r[0]), "=r"(r[1]), "=r"(r[2]), "=r"(r[3]) : "r"(addr));
}
__device__ __forceinline__ void ldm4t(uint32_t* r, uint32_t addr) {
    asm volatile("ldmatrix.sync.aligned.m8n8.x4.trans.shared.b16 {%0,%1,%2,%3}, [%4];"
                 : "=r"(r[0]), "=r"(r[1]), "=r"(r[2]), "=r"(r[3]) : "r"(addr));
}
__device__ __forceinline__ void mma16816(float* d, const uint32_t* a,
                                         uint32_t b0, uint32_t b1) {
    asm("mma.sync.aligned.m16n8k16.row.col.f32.f16.f16.f32 "
        "{%0,%1,%2,%3}, {%4,%5,%6,%7}, {%8,%9}, {%0,%1,%2,%3};"
        : "+f"(d[0]), "+f"(d[1]), "+f"(d[2]), "+f"(d[3])
        : "r"(a[0]), "r"(a[1]), "r"(a[2]), "r"(a[3]), "r"(b0), "r"(b1));
}
// pack two fp32 -> fp16x2 (a in low half, b in high half)
__device__ __forceinline__ uint32_t pack_h2(float a, float b) {
    uint32_t r;
    asm("cvt.rn.f16x2.f32 %0, %1, %2;" : "=r"(r) : "f"(b), "f"(a));
    return r;
}
// swizzled 16B-chunk offset within a row (conflict-free ldmatrix)
#define SWC(chunk, row) ((((chunk) ^ ((row) & 7)) << 4))

// ---- prep kernel: W[c][h] fp32 -> W^T[h][c] fp16 --------------------------
__global__ void prep_w(const float* __restrict__ Wk,
                       const float* __restrict__ Wq,
                       const float* __restrict__ Wv)
{
    int idx = blockIdx.x * 256 + threadIdx.x;   // 49152 total
    int m = idx >> 14;
    int r = idx & 16383;
    int h = r >> 8, c = r & 255;
    const float* W = (m == 0) ? Wk : ((m == 1) ? Wq : Wv);
    g_Wt[idx] = __float2half_rn(W[c * 64 + h]);
}

// ---- main kernel ----------------------------------------------------------
__global__ void __launch_bounds__(NT, 2)
head_mma(const float* __restrict__ x, float* __restrict__ out)
{
    extern __shared__ char sm[];
    const uint32_t smb = smem_u32(sm);
    const int tid = threadIdx.x, lane = tid & 31, wid = tid >> 5;
    const float* xb = x + (size_t)blockIdx.x * (T_ * C_);

    // ================= Phase 1: QKV projections (K in 2 chunks) ===========
    float pacc[3][2][4][4];
#pragma unroll
    for (int m = 0; m < 3; m++)
#pragma unroll
        for (int mt = 0; mt < 2; mt++)
#pragma unroll
            for (int nt = 0; nt < 4; nt++)
#pragma unroll
                for (int i = 0; i < 4; i++) pacc[m][mt][nt][i] = 0.f;

    const int mr = (wid & 3) * 32;      // warp M-block (rows)
    const int nc = (wid >> 2) * 32;     // warp N-block (cols within matrix)

#pragma unroll
    for (int chunk = 0; chunk < 2; chunk++) {
        __syncthreads();   // previous chunk's MMAs done -> X/W writable

        // stage X chunk [128 rows][128 cols] fp32 -> fp16 swizzled
#pragma unroll 4
        for (int it = 0; it < 32; it++) {
            int u = tid + (it << 8);          // half2 index, 8192 total
            int row = u >> 6, cp = u & 63;
            float2 v = *(const float2*)(xb + row * C_ + chunk * 128 + 2 * cp);
            uint32_t off = row * 256 + SWC(cp >> 2, row) + ((cp & 3) << 2);
            *(uint32_t*)(sm + SM_X + off) = pack_h2(v.x, v.y);
        }

#pragma unroll
        for (int m = 0; m < 3; m++) {
            if (m > 0) __syncthreads();   // prev m's MMAs done -> W writable
            // stage W(m, chunk): [64 h-rows][128 cols] fp16
            const uint32_t* srcW = (const uint32_t*)(g_Wt + m * 16384);
#pragma unroll 4
            for (int it = 0; it < 16; it++) {
                int u = tid + (it << 8);      // half2 index, 4096 total
                int hr = u >> 6, cp = u & 63;
                uint32_t off = hr * 256 + SWC(cp >> 2, hr) + ((cp & 3) << 2);
                *(uint32_t*)(sm + SM_W + off) = srcW[hr * 128 + chunk * 64 + cp];
            }
            __syncthreads();

#pragma unroll 2
            for (int ks = 0; ks < 8; ks++) {
                uint32_t ah[2][4];
#pragma unroll
                for (int mt = 0; mt < 2; mt++) {
                    int ar = mr + 16 * mt + (lane & 15);
                    ldm4(ah[mt], smb + SM_X + ar * 256
                                 + SWC(2 * ks + (lane >> 4), ar));
                }
#pragma unroll
                for (int n16 = 0; n16 < 2; n16++) {
                    uint32_t bh[4];
                    int bn = nc + 16 * n16 + ((lane >> 3) & 1) * 8 + (lane & 7);
                    ldm4(bh, smb + SM_W + bn * 256
                             + SWC(2 * ks + (lane >> 4), bn));
#pragma unroll
                    for (int mt = 0; mt < 2; mt++)
#pragma unroll
                        for (int j = 0; j < 2; j++)
                            mma16816(pacc[m][mt][2 * n16 + j],
                                     ah[mt], bh[j], bh[j + 2]);
                }
            }
        }
    }
    __syncthreads();   // all proj MMAs done; overlay attn region

    // ---- spill K/Q/V as fp16 tiles [row][h], Q pre-scaled by 2^-4 --------
#pragma unroll
    for (int m = 0; m < 3; m++) {
        uint32_t base = (m == 0) ? SM_K : ((m == 1) ? SM_Q : SM_V);
        float scale = (m == 1) ? 0.0625f : 1.0f;
#pragma unroll
        for (int mt = 0; mt < 2; mt++)
#pragma unroll
            for (int nt = 0; nt < 4; nt++) {
                float* d = pacc[m][mt][nt];
                int sra = mr + 16 * mt + (lane >> 2), srb = sra + 8;
                int c = nc + 8 * nt + 2 * (lane & 3);
                uint32_t o0 = sra * 128 + SWC(c >> 3, sra) + ((c & 7) << 1);
                uint32_t o1 = srb * 128 + SWC(c >> 3, srb) + ((c & 7) << 1);
                *(uint32_t*)(sm + base + o0) = pack_h2(d[0] * scale, d[1] * scale);
                *(uint32_t*)(sm + base + o1) = pack_h2(d[2] * scale, d[3] * scale);
            }
    }
    __syncthreads();

    // ---- load Q fragments into registers (frees Q smem region for P) -----
    const int r16 = wid * 16;
    uint32_t qf[4][4];
#pragma unroll
    for (int ks = 0; ks < 4; ks++) {
        int ar = r16 + (lane & 15);
        ldm4(qf[ks], smb + SM_Q + ar * 128 + SWC(2 * ks + (lane >> 4), ar));
    }
    __syncthreads();   // everyone has Q; P may now overwrite

    // ================= Phase 2: flash-style attention ======================
    const int ra = r16 + (lane >> 2), rb = ra + 8;
    float m0 = -1e30f, m1 = -1e30f, l0 = 0.f, l1 = 0.f;
    float oacc[8][4];
#pragma unroll
    for (int nt = 0; nt < 8; nt++)
#pragma unroll
        for (int i = 0; i < 4; i++) oacc[nt][i] = 0.f;

    const int cmax = (wid < 4) ? 1 : 2;
    for (int c = 0; c < cmax; c++) {
        // ---- S chunk: rows [r16,r16+16) x cols [64c, 64c+64) ----
        float sacc[8][4];
#pragma unroll
        for (int nt = 0; nt < 8; nt++)
#pragma unroll
            for (int i = 0; i < 4; i++) sacc[nt][i] = 0.f;

#pragma unroll
        for (int ks = 0; ks < 4; ks++) {
#pragma unroll
            for (int n16 = 0; n16 < 4; n16++) {
                if (4 * c + n16 <= wid) {
                    int bn = 64 * c + 16 * n16
                           + ((lane >> 3) & 1) * 8 + (lane & 7);
                    uint32_t kh[4];
                    ldm4(kh, smb + SM_K + bn * 128
                             + SWC(2 * ks + (lane >> 4), bn));
#pragma unroll
                    for (int j = 0; j < 2; j++)
                        mma16816(sacc[2 * n16 + j], qf[ks], kh[j], kh[j + 2]);
                }
            }
        }

        // ---- causal mask + online softmax update (warp-local) ----
        float cm0 = -1e30f, cm1 = -1e30f;
#pragma unroll
        for (int nt = 0; nt < 8; nt++) {
            bool act = (4 * c + (nt >> 1)) <= wid;
            int s0 = 64 * c + 8 * nt + 2 * (lane & 3);
            float v0 = (act && s0 <= ra)     ? sacc[nt][0] : -1e30f;
            float v1 = (act && s0 + 1 <= ra) ? sacc[nt][1] : -1e30f;
            float v2 = (act && s0 <= rb)     ? sacc[nt][2] : -1e30f;
            float v3 = (act && s0 + 1 <= rb) ? sacc[nt][3] : -1e30f;
            sacc[nt][0] = v0; sacc[nt][1] = v1;
            sacc[nt][2] = v2; sacc[nt][3] = v3;
            cm0 = fmaxf(cm0, fmaxf(v0, v1));
            cm1 = fmaxf(cm1, fmaxf(v2, v3));
        }
        cm0 = fmaxf(cm0, __shfl_xor_sync(0xFFFFFFFFu, cm0, 1));
        cm0 = fmaxf(cm0, __shfl_xor_sync(0xFFFFFFFFu, cm0, 2));
        cm1 = fmaxf(cm1, __shfl_xor_sync(0xFFFFFFFFu, cm1, 1));
        cm1 = fmaxf(cm1, __shfl_xor_sync(0xFFFFFFFFu, cm1, 2));

        float mn0 = fmaxf(m0, cm0), mn1 = fmaxf(m1, cm1);
        float a0 = __expf(m0 - mn0), a1 = __expf(m1 - mn1);
        float cs0 = 0.f, cs1 = 0.f;
#pragma unroll
        for (int nt = 0; nt < 8; nt++) {
            float e0 = (sacc[nt][0] > -1e29f) ? __expf(sacc[nt][0] - mn0) : 0.f;
            float e1 = (sacc[nt][1] > -1e29f) ? __expf(sacc[nt][1] - mn0) : 0.f;
            float e2 = (sacc[nt][2] > -1e29f) ? __expf(sacc[nt][2] - mn1) : 0.f;
            float e3 = (sacc[nt][3] > -1e29f) ? __expf(sacc[nt][3] - mn1) : 0.f;
            sacc[nt][0] = e0; sacc[nt][1] = e1;
            sacc[nt][2] = e2; sacc[nt][3] = e3;
            cs0 += e0 + e1;
            cs1 += e2 + e3;
        }
        cs0 += __shfl_xor_sync(0xFFFFFFFFu, cs0, 1);
        cs0 += __shfl_xor_sync(0xFFFFFFFFu, cs0, 2);
        cs1 += __shfl_xor_sync(0xFFFFFFFFu, cs1, 1);
        cs1 += __shfl_xor_sync(0xFFFFFFFFu, cs1, 2);
        l0 = l0 * a0 + cs0;
        l1 = l1 * a1 + cs1;
        m0 = mn0; m1 = mn1;

        // rescale running O
#pragma unroll
        for (int nt = 0; nt < 8; nt++) {
            oacc[nt][0] *= a0; oacc[nt][1] *= a0;
            oacc[nt][2] *= a1; oacc[nt][3] *= a1;
        }

        // ---- store P chunk (warp-private rows) fp16 ----
#pragma unroll
        for (int nt = 0; nt < 8; nt++) {
            if ((4 * c + (nt >> 1)) <= wid) {
                int c0 = 8 * nt + 2 * (lane & 3);   // chunk-local col
                uint32_t o0 = ra * 128 + SWC(c0 >> 3, ra) + ((c0 & 7) << 1);
                uint32_t o1 = rb * 128 + SWC(c0 >> 3, rb) + ((c0 & 7) << 1);
                *(uint32_t*)(sm + SM_Q + o0) = pack_h2(sacc[nt][0], sacc[nt][1]);
                *(uint32_t*)(sm + SM_Q + o1) = pack_h2(sacc[nt][2], sacc[nt][3]);
            }
        }
        __syncwarp();

        // ---- O += P_chunk @ V_chunk ----
#pragma unroll
        for (int ks2 = 0; ks2 < 4; ks2++) {
            if (4 * c + ks2 <= wid) {
                int par = r16 + (lane & 15);
                uint32_t ph[4];
                ldm4(ph, smb + SM_Q + par * 128
                         + SWC(2 * ks2 + (lane >> 4), par));
#pragma unroll
                for (int ntv = 0; ntv < 4; ntv++) {
                    int vr = 64 * c + 16 * ks2 + (lane & 15);
                    uint32_t vh[4];
                    ldm4t(vh, smb + SM_V + vr * 128
                              + SWC(2 * ntv + (lane >> 4), vr));
#pragma unroll
                    for (int j = 0; j < 2; j++)
                        mma16816(oacc[2 * ntv + j],
                                 ph, vh[2 * j], vh[2 * j + 1]);
                }
            }
        }
        __syncwarp();   // P reads done before next chunk overwrites
    }

    // ---- normalize + write out -------------------------------------------
    float inv0 = 1.f / l0, inv1 = 1.f / l1;
    float* ob = out + (size_t)blockIdx.x * (T_ * H_);
#pragma unroll
    for (int nt = 0; nt < 8; nt++) {
        int c0 = 8 * nt + 2 * (lane & 3);
        *(float2*)(ob + ra * 64 + c0) =
            make_float2(oacc[nt][0] * inv0, oacc[nt][1] * inv0);
        *(float2*)(ob + rb * 64 + c0) =
            make_float2(oacc[nt][2] * inv1, oacc[nt][3] * inv1);
    }
}

extern "C" void kernel_launch(void* const* d_in, const int* in_sizes, int n_in,
                              void* d_out, int out_size) {
    const float* x  = (const float*)d_in[0];
    const float* Wk = (const float*)d_in[1];
    const float* Wq = (const float*)d_in[2];
    const float* Wv = (const float*)d_in[3];
    float* out = (float*)d_out;

    prep_w<<<192, 256>>>(Wk, Wq, Wv);

    cudaFuncSetAttribute(head_mma,
                         cudaFuncAttributeMaxDynamicSharedMemorySize,
                         SMEM_BYTES);
    head_mma<<<B_, NT, SMEM_BYTES>>>(x, out);
}